// round 9
// baseline (speedup 1.0000x reference)
#include <cuda_runtime.h>
#include <math.h>

// Problem constants (fixed by the dataset)
#define NB   8192      // batch rows
#define NV   32000     // vocab (row length)
#define NK   5         // negatives per row
#define NS   100       // sampling-domain columns of prob
#define EPSF 1e-10f

#define RPT  2                     // rows per thread
#define NTHR 64
#define NCTA (NB / (NTHR * RPT))   // 64 CTAs
#define HALF (NB / RPT)            // 4096: row stride between a thread's rows

// Scratch for the fused cross-block reduction (no allocs allowed)
__device__ float g_partial[NCTA];
__device__ int   g_ticket = 0;   // re-armed to 0 by the last block each call

// The detached row-max shift cancels exactly in out = terms / sum(terms),
// so no pass over yHat is needed — just 6 gathered logits per row (ind[] <
// 100, plus the target column y[b]). Latency-bound: 2 rows/thread doubles
// in-flight gathers (22 per thread) and halves the same-address ticket
// atomics in the tail.
__device__ __forceinline__ float row_loss(
    const float* __restrict__ yHat,
    const float* __restrict__ prob,
    int b, int yb, const int* id,
    float tg, const float* pr, const float* cj)
{
    float p[NK], q = INFINITY;
    #pragma unroll
    for (int j = 0; j < NK; ++j) {
        p[j] = __frcp_rn(pr[j]);
        q = fminf(q, p[j]);
    }
    float t[NK];
    float t0 = q * __expf(tg);
    float S  = t0;
    #pragma unroll
    for (int j = 0; j < NK; ++j) {
        t[j] = p[j] * __expf(cj[j]);
        S += t[j];
    }
    const float inv = 1.0f / S;
    float acc = __logf(t0 * inv + EPSF);
    #pragma unroll
    for (int j = 0; j < NK; ++j)
        acc += __logf(1.0f - t[j] * inv + EPSF);
    return acc;
}

__global__ __launch_bounds__(NTHR, 1) void blackout_fused_kernel(
    const float* __restrict__ yHat,
    const float* __restrict__ prob,
    const int*   __restrict__ y,
    const int*   __restrict__ ind,
    float*       __restrict__ out)
{
    const int t  = blockIdx.x * NTHR + threadIdx.x;   // 0..4095
    const int b0 = t;                                  // row A
    const int b1 = t + HALF;                           // row B (coalesced too)

    // ---- level 0: coalesced index loads (L2-hot across graph replays) ----
    const int y0 = __ldg(&y[b0]);
    const int y1 = __ldg(&y[b1]);
    int id0[NK], id1[NK];
    #pragma unroll
    for (int j = 0; j < NK; ++j) id0[j] = __ldg(&ind[b0 * NK + j]);
    #pragma unroll
    for (int j = 0; j < NK; ++j) id1[j] = __ldg(&ind[b1 * NK + j]);

    // ---- level 1: ALL 22 data gathers issued before any math ----
    const float* __restrict__ prow0 = prob + (long long)y0 * NS;
    const float* __restrict__ prow1 = prob + (long long)y1 * NS;
    const float* __restrict__ rowf0 = yHat + (long long)b0 * NV;
    const float* __restrict__ rowf1 = yHat + (long long)b1 * NV;

    const float tg0 = __ldg(&rowf0[y0]);   // truly-random target gathers
    const float tg1 = __ldg(&rowf1[y1]);
    float pr0[NK], cj0[NK], pr1[NK], cj1[NK];
    #pragma unroll
    for (int j = 0; j < NK; ++j) {
        pr0[j] = __ldg(&prow0[id0[j]]);
        pr1[j] = __ldg(&prow1[id1[j]]);
    }
    #pragma unroll
    for (int j = 0; j < NK; ++j) {
        cj0[j] = __ldg(&rowf0[id0[j]]);
        cj1[j] = __ldg(&rowf1[id1[j]]);
    }

    // ---- math tail (max shift cancels in the ratio) ----
    float acc = row_loss(yHat, prob, b0, y0, id0, tg0, pr0, cj0)
              + row_loss(yHat, prob, b1, y1, id1, tg1, pr1, cj1);

    // ---- deterministic block reduction (64 -> 1) ----
    __shared__ float sw[2];
    #pragma unroll
    for (int o = 16; o; o >>= 1) acc += __shfl_xor_sync(0xffffffffu, acc, o);
    const int lane = threadIdx.x & 31;
    const int wid  = threadIdx.x >> 5;
    if (lane == 0) sw[wid] = acc;
    __syncthreads();

    __shared__ int s_last;
    if (threadIdx.x == 0) {
        g_partial[blockIdx.x] = sw[0] + sw[1];
        __threadfence();                         // publish partial to L2
        int t_ = atomicAdd(&g_ticket, 1);        // last block does the final sum
        s_last = (t_ == NCTA - 1);
    }
    __syncthreads();

    if (s_last && threadIdx.x < 32) {
        // volatile: bypass this SM's (non-coherent) L1 when reading partials
        // produced by other SMs. Fixed order -> deterministic.
        volatile float* gp = g_partial;
        float v = 0.0f;
        #pragma unroll
        for (int k = 0; k < NCTA / 32; ++k)      // 64 partials, 2 per lane
            v += gp[k * 32 + threadIdx.x];
        #pragma unroll
        for (int o = 16; o; o >>= 1) v += __shfl_xor_sync(0xffffffffu, v, o);
        if (threadIdx.x == 0) {
            out[0] = -v / (float)(NB * (NK + 1));
            g_ticket = 0;                        // re-arm for next graph replay
        }
    }
}

extern "C" void kernel_launch(void* const* d_in, const int* in_sizes, int n_in,
                              void* d_out, int out_size)
{
    const float* yHat = (const float*)d_in[0];   // [8192, 32000] f32
    const float* prob = (const float*)d_in[1];   // [32000, 100] f32
    const int*   y    = (const int*)d_in[2];     // [8192] i32
    const int*   ind  = (const int*)d_in[3];     // [8192, 5] i32
    float* out = (float*)d_out;

    blackout_fused_kernel<<<NCTA, NTHR>>>(yHat, prob, y, ind, out);
}

// round 10
// speedup vs baseline: 1.0187x; 1.0187x over previous
#include <cuda_runtime.h>
#include <math.h>

// Problem constants (fixed by the dataset)
#define NB   8192      // batch rows
#define NV   32000     // vocab (row length)
#define NK   5         // negatives per row
#define NS   100       // sampling-domain columns of prob
#define EPSF 1e-10f

#define NCTA 128       // 128 CTAs x 64 threads = 8192 = one thread per row
#define NTHR 64

// Scratch for the fused cross-block reduction (no allocs allowed)
__device__ float g_partial[NCTA];
__device__ int   g_ticket = 0;   // re-armed to 0 by the last block each call

// The detached row-max shift cancels exactly in out = terms / sum(terms),
// so no pass over yHat is needed — just 6 gathered logits per row (ind[] <
// 100, plus the target column y[b]). Latency-bound; tail uses a fused
// release-atomic ticket (no separate __threadfence round-trip).
__global__ __launch_bounds__(NTHR, 1) void blackout_fused_kernel(
    const float* __restrict__ yHat,
    const float* __restrict__ prob,
    const int*   __restrict__ y,
    const int*   __restrict__ ind,
    float*       __restrict__ out)
{
    const int b = blockIdx.x * NTHR + threadIdx.x;   // 0..8191, exact cover

    // ---- level 0: coalesced index loads (L2-hot across graph replays) ----
    const int yb = __ldg(&y[b]);
    int id[NK];
    #pragma unroll
    for (int j = 0; j < NK; ++j) id[j] = __ldg(&ind[b * NK + j]);

    // ---- level 1: ALL 11 data gathers issued before any math ----
    const float* __restrict__ prow = prob + (long long)yb * NS;
    const float* __restrict__ rowf = yHat + (long long)b * NV;

    float pr[NK], cj[NK];
    const float tg = __ldg(&rowf[yb]);            // truly-random target gather
    #pragma unroll
    for (int j = 0; j < NK; ++j) pr[j] = __ldg(&prow[id[j]]);
    #pragma unroll
    for (int j = 0; j < NK; ++j) cj[j] = __ldg(&rowf[id[j]]);

    // ---- math tail (MUFU intrinsics; max shift cancels in the ratio) ----
    float p[NK], q = INFINITY;
    #pragma unroll
    for (int j = 0; j < NK; ++j) {
        p[j] = __frcp_rn(pr[j]);
        q = fminf(q, p[j]);
    }

    float t[NK];
    float t0 = q * __expf(tg);
    float S  = t0;
    #pragma unroll
    for (int j = 0; j < NK; ++j) {
        t[j] = p[j] * __expf(cj[j]);
        S += t[j];
    }
    const float inv = 1.0f / S;

    float acc = __logf(t0 * inv + EPSF);          // log(out_0 + eps)
    #pragma unroll
    for (int j = 0; j < NK; ++j)
        acc += __logf(1.0f - t[j] * inv + EPSF);  // log(1 - out_j + eps)

    // ---- deterministic block reduction (64 -> 1) ----
    __shared__ float sw[2];
    #pragma unroll
    for (int o = 16; o; o >>= 1) acc += __shfl_xor_sync(0xffffffffu, acc, o);
    const int lane = threadIdx.x & 31;
    const int wid  = threadIdx.x >> 5;
    if (lane == 0) sw[wid] = acc;
    __syncthreads();

    __shared__ int s_last;
    if (threadIdx.x == 0) {
        g_partial[blockIdx.x] = sw[0] + sw[1];
        // release-atomic ticket: orders the partial store without a separate
        // MEMBAR.GPU round-trip. Last block to arrive does the final sum.
        int t_;
        asm volatile("atom.add.release.gpu.u32 %0, [%1], 1;"
                     : "=r"(t_) : "l"(&g_ticket) : "memory");
        s_last = (t_ == NCTA - 1);
    }
    __syncthreads();

    if (s_last && threadIdx.x < 32) {
        // acquire fence pairs with the producers' release-atomics; then
        // volatile reads bypass this SM's (non-coherent) L1. Fixed order ->
        // deterministic.
        if (threadIdx.x == 0)
            asm volatile("fence.acquire.gpu;" ::: "memory");
        __syncwarp();
        volatile float* gp = g_partial;
        float v = 0.0f;
        #pragma unroll
        for (int k = 0; k < NCTA / 32; ++k)      // 128 partials, 4 per lane
            v += gp[k * 32 + threadIdx.x];
        #pragma unroll
        for (int o = 16; o; o >>= 1) v += __shfl_xor_sync(0xffffffffu, v, o);
        if (threadIdx.x == 0) {
            out[0] = -v / (float)(NB * (NK + 1));
            g_ticket = 0;                        // re-arm for next graph replay
        }
    }
}

extern "C" void kernel_launch(void* const* d_in, const int* in_sizes, int n_in,
                              void* d_out, int out_size)
{
    const float* yHat = (const float*)d_in[0];   // [8192, 32000] f32
    const float* prob = (const float*)d_in[1];   // [32000, 100] f32
    const int*   y    = (const int*)d_in[2];     // [8192] i32
    const int*   ind  = (const int*)d_in[3];     // [8192, 5] i32
    float* out = (float*)d_out;

    blackout_fused_kernel<<<NCTA, NTHR>>>(yHat, prob, y, ind, out);
}